// round 3
// baseline (speedup 1.0000x reference)
#include <cuda_runtime.h>
#include <cstdint>

#define N_ROWS 100000
#define IN_CH  256
#define OUT_CH 128
#define KVOL   8

#define BM 128
#define BN 128      // == OUT_CH: one kernel-offset kb per blockIdx.x
#define BK 32
#define NCHUNK 8    // IN_CH / BK

// A fragment tile: [ks(4)][m16(8)][g(8)][l4(4)][reg(4)] = 4096 floats = 16KB
// B fragment tile: [ks(4)][c(128)][l4(4)][j(2)]         = 4096 floats = 16KB
#define TILE_FLOATS 4096
#define SM_BYTES (4 * TILE_FLOATS * 4)   // 2 bufs A + 2 bufs B = 64KB

__device__ uint32_t g_Wt[KVOL * NCHUNK * TILE_FLOATS];   // pre-cvt + pre-packed W

__device__ __forceinline__ uint32_t f2tf32(float x) {
    uint32_t u;
    asm("cvt.rna.tf32.f32 %0, %1;" : "=r"(u) : "f"(x));
    return u;
}
__device__ __forceinline__ uint32_t smem_u32(const void* p) {
    uint32_t a;
    asm("{ .reg .u64 t; cvta.to.shared.u64 t, %1; cvt.u32.u64 %0, t; }" : "=r"(a) : "l"(p));
    return a;
}
__device__ __forceinline__ int aIdx(int ks, int m16, int g, int l4, int reg) {
    return (((ks * 8 + m16) * 8 + g) * 4 + l4) * 4 + reg;
}
__device__ __forceinline__ int bIdx(int ks, int c, int l4, int j) {
    return ((ks * 128 + c) * 4 + l4) * 2 + j;
}

// ---------------------------------------------------------------------------
// prep: W [8][256][128] -> tf32, packed in B-fragment order per [kb][chunk]
__global__ __launch_bounds__(256)
void prep_Wt(const float* __restrict__ W)
{
    int d = blockIdx.x * blockDim.x + threadIdx.x;   // 0 .. 8*8*4096-1
    int kb = d >> 15;
    int c  = (d >> 12) & 7;
    int r  = d & 4095;
    int ks = r >> 10;
    int cn = (r >> 3) & 127;
    int l4 = (r >> 1) & 3;
    int j  = r & 1;
    int kglob = c * BK + ks * 8 + l4 + 4 * j;
    float v = W[((size_t)kb * IN_CH + kglob) * OUT_CH + cn];
    g_Wt[d] = f2tf32(v);
}

// ---------------------------------------------------------------------------
__global__ __launch_bounds__(256, 2)
void gemm_tf32(const float* __restrict__ A, float* __restrict__ out)
{
    extern __shared__ float smem[];
    float* Af[2] = { smem,                  smem + TILE_FLOATS };
    float* Bf[2] = { smem + 2*TILE_FLOATS, smem + 3*TILE_FLOATS };

    const int tid  = threadIdx.x;
    const int kb   = blockIdx.x;
    const int m0   = blockIdx.y * BM;
    const int lane = tid & 31;
    const int wid  = tid >> 5;
    const int wm   = (wid >> 1) * 32;       // warp M offset
    const int wn   = (wid & 1) * 64;        // warp N offset
    const int m16b = wm >> 4;
    const int g    = lane >> 2;
    const int l4   = lane & 3;

    // staging mapping for A: thread -> (m16, g2) row pair + 8-wide k segment
    const int pr   = tid >> 2;
    const int sm16 = pr >> 3;
    const int sg   = pr & 7;
    const int kseg = (tid & 3) * 8;         // 0,8,16,24
    const int sks  = kseg >> 3;
    const int r0g  = m0 + sm16 * 16 + sg;   // global row (h=0)
    const int r1g  = r0g + 8;               // global row (h=1)

    float4 av[4];
    auto ldA = [&](int c) {
        const float* base = A + (size_t)0;
        int k0 = c * BK + kseg;
        if (r0g < N_ROWS) {
            av[0] = *(const float4*)(base + (size_t)r0g * IN_CH + k0);
            av[1] = *(const float4*)(base + (size_t)r0g * IN_CH + k0 + 4);
        } else { av[0] = av[1] = make_float4(0.f,0.f,0.f,0.f); }
        if (r1g < N_ROWS) {
            av[2] = *(const float4*)(base + (size_t)r1g * IN_CH + k0);
            av[3] = *(const float4*)(base + (size_t)r1g * IN_CH + k0 + 4);
        } else { av[2] = av[3] = make_float4(0.f,0.f,0.f,0.f); }
    };
    auto stA = [&](int buf) {
        float* dst = Af[buf];
        const float* v0 = &av[0].x;  // j=0 rows r0
        const float* v2 = &av[2].x;  // j=0 rows r1
        const float* v1 = &av[1].x;  // j=1 rows r0
        const float* v3 = &av[3].x;  // j=1 rows r1
        #pragma unroll
        for (int l = 0; l < 4; ++l) {
            uint2 p0 = make_uint2(f2tf32(v0[l]), f2tf32(v2[l]));
            *(uint2*)(dst + aIdx(sks, sm16, sg, l, 0)) = p0;
            uint2 p1 = make_uint2(f2tf32(v1[l]), f2tf32(v3[l]));
            *(uint2*)(dst + aIdx(sks, sm16, sg, l, 2)) = p1;
        }
    };
    auto cpB = [&](int c, int buf) {
        const float* src = (const float*)g_Wt + ((size_t)(kb * NCHUNK + c)) * TILE_FLOATS;
        uint32_t dst = smem_u32(Bf[buf]);
        #pragma unroll
        for (int i = 0; i < 4; ++i) {
            int off = (tid + i * 256) * 4;   // floats
            asm volatile("cp.async.cg.shared.global [%0], [%1], 16;"
                         :: "r"(dst + off * 4), "l"(src + off) : "memory");
        }
        asm volatile("cp.async.commit_group;" ::: "memory");
    };

    float acc[2][8][4];
    #pragma unroll
    for (int mt = 0; mt < 2; ++mt)
        #pragma unroll
        for (int nt = 0; nt < 8; ++nt)
            #pragma unroll
            for (int i = 0; i < 4; ++i) acc[mt][nt][i] = 0.f;

    auto compute = [&](int buf) {
        const float* Ab = Af[buf];
        const float* Bb = Bf[buf];
        #pragma unroll
        for (int ks = 0; ks < 4; ++ks) {
            uint4 a0 = *(const uint4*)(Ab + aIdx(ks, m16b,     g, l4, 0));
            uint4 a1 = *(const uint4*)(Ab + aIdx(ks, m16b + 1, g, l4, 0));
            #pragma unroll
            for (int nt = 0; nt < 8; ++nt) {
                uint2 b = *(const uint2*)(Bb + bIdx(ks, wn + nt * 8 + g, l4, 0));
                asm volatile(
                    "mma.sync.aligned.m16n8k8.row.col.f32.tf32.tf32.f32 "
                    "{%0,%1,%2,%3}, {%4,%5,%6,%7}, {%8,%9}, {%0,%1,%2,%3};\n"
                    : "+f"(acc[0][nt][0]), "+f"(acc[0][nt][1]),
                      "+f"(acc[0][nt][2]), "+f"(acc[0][nt][3])
                    : "r"(a0.x), "r"(a0.y), "r"(a0.z), "r"(a0.w),
                      "r"(b.x), "r"(b.y));
                asm volatile(
                    "mma.sync.aligned.m16n8k8.row.col.f32.tf32.tf32.f32 "
                    "{%0,%1,%2,%3}, {%4,%5,%6,%7}, {%8,%9}, {%0,%1,%2,%3};\n"
                    : "+f"(acc[1][nt][0]), "+f"(acc[1][nt][1]),
                      "+f"(acc[1][nt][2]), "+f"(acc[1][nt][3])
                    : "r"(a1.x), "r"(a1.y), "r"(a1.z), "r"(a1.w),
                      "r"(b.x), "r"(b.y));
            }
        }
    };

    // prologue
    ldA(0);
    cpB(0, 0);
    stA(0);
    asm volatile("cp.async.wait_group 0;" ::: "memory");
    __syncthreads();

    #pragma unroll 1
    for (int c = 0; c < NCHUNK; ++c) {
        const int buf = c & 1;
        if (c + 1 < NCHUNK) { ldA(c + 1); cpB(c + 1, buf ^ 1); }
        compute(buf);
        if (c + 1 < NCHUNK) {
            stA(buf ^ 1);
            asm volatile("cp.async.wait_group 0;" ::: "memory");
        }
        __syncthreads();
    }

    // epilogue: direct register stores; out[(n*8+kb)*128 + col]
    #pragma unroll
    for (int mt = 0; mt < 2; ++mt) {
        const int r0 = m0 + wm + mt * 16 + g;
        const int r1 = r0 + 8;
        #pragma unroll
        for (int nt = 0; nt < 8; ++nt) {
            const int col = wn + nt * 8 + l4 * 2;
            if (r0 < N_ROWS) {
                *(float2*)(out + ((size_t)r0 * KVOL + kb) * OUT_CH + col) =
                    make_float2(acc[mt][nt][0], acc[mt][nt][1]);
            }
            if (r1 < N_ROWS) {
                *(float2*)(out + ((size_t)r1 * KVOL + kb) * OUT_CH + col) =
                    make_float2(acc[mt][nt][2], acc[mt][nt][3]);
            }
        }
    }
}

// ---------------------------------------------------------------------------
__global__ __launch_bounds__(256)
void coords_kernel(const int* __restrict__ coords, float* __restrict__ out)
{
    int i = blockIdx.x * blockDim.x + threadIdx.x;   // over N_ROWS*KVOL
    if (i >= N_ROWS * KVOL) return;
    int n = i >> 3, k = i & 7;
    int cx = __ldg(coords + n * 3 + 0);
    int cy = __ldg(coords + n * 3 + 1);
    int cz = __ldg(coords + n * 3 + 2);
    out[(size_t)i * 3 + 0] = (float)(2 * cx + ((k >> 2) & 1));
    out[(size_t)i * 3 + 1] = (float)(2 * cy + ((k >> 1) & 1));
    out[(size_t)i * 3 + 2] = (float)(2 * cz + (k & 1));
}

// ---------------------------------------------------------------------------
extern "C" void kernel_launch(void* const* d_in, const int* in_sizes, int n_in,
                              void* d_out, int out_size)
{
    const float* feats  = nullptr;
    const int*   coords = nullptr;
    const float* W      = nullptr;
    for (int i = 0; i < n_in; ++i) {
        if      (in_sizes[i] == N_ROWS * IN_CH)        feats  = (const float*)d_in[i];
        else if (in_sizes[i] == N_ROWS * 3)            coords = (const int*)d_in[i];
        else if (in_sizes[i] == KVOL * IN_CH * OUT_CH) W      = (const float*)d_in[i];
    }
    float* out = (float*)d_out;

    cudaFuncSetAttribute(gemm_tf32,
                         cudaFuncAttributeMaxDynamicSharedMemorySize, SM_BYTES);

    prep_Wt<<<(KVOL * NCHUNK * TILE_FLOATS) / 256, 256>>>(W);

    dim3 grid(KVOL, (N_ROWS + BM - 1) / BM);   // kb fastest: 8 CTAs share A tile in L2
    gemm_tf32<<<grid, 256, SM_BYTES>>>(feats, out);

    const long long featsN = (long long)N_ROWS * KVOL * OUT_CH;
    const long long coordN = (long long)N_ROWS * KVOL * 3;
    if ((long long)out_size >= featsN + coordN && coords != nullptr) {
        const int total = N_ROWS * KVOL;
        coords_kernel<<<(total + 255) / 256, 256>>>(coords, out + featsN);
    }
}

// round 4
// speedup vs baseline: 2.0973x; 2.0973x over previous
#include <cuda_runtime.h>
#include <cuda_fp16.h>
#include <cstdint>

#define N_ROWS 100000
#define IN_CH  256
#define OUT_CH 128
#define KVOL   8

#define BM 128
#define BK 32
#define NCHUNK 8                 // IN_CH / BK
#define MTILES 782               // ceil(100000/128)

// fragment-packed tiles, half2 units (uint32)
// A chunk tile: [ks(2)][m16(8)][g(8)][l4(4)][reg(4)] = 2048 half2 = 8KB
// B chunk tile: [ks(2)][col(128)][l4(4)][j(2)]        = 2048 half2 = 8KB
#define CH_U32 2048
#define SM_U32 (4 * CH_U32)      // 2 bufs A + 2 bufs B = 32KB

__device__ __align__(16) uint32_t g_At[MTILES * NCHUNK * CH_U32];   // 51.25MB
__device__ __align__(16) uint32_t g_Wt[KVOL * NCHUNK * CH_U32];     // 512KB

__device__ __forceinline__ uint32_t pack_h2(float a, float b) {
    __half2 h = __floats2half2_rn(a, b);
    return *reinterpret_cast<uint32_t*>(&h);
}
__device__ __forceinline__ uint32_t smem_u32(const void* p) {
    uint32_t a;
    asm("{ .reg .u64 t; cvta.to.shared.u64 t, %1; cvt.u32.u64 %0, t; }" : "=r"(a) : "l"(p));
    return a;
}
__device__ __forceinline__ int aIdx(int ks, int m16, int g, int l4, int reg) {
    return (((ks * 8 + m16) * 8 + g) * 4 + l4) * 4 + reg;
}

// ---------------------------------------------------------------------------
// pack A: [100000,256] fp32 -> per-tile fp16 MMA fragments
__global__ __launch_bounds__(256)
void prep_At(const float* __restrict__ A)
{
    const int tile = blockIdx.x;
    const int m0 = tile * BM;
    const int tid = threadIdx.x;
    const int pr = tid >> 2;
    const int sm16 = pr >> 3;
    const int sg = pr & 7;
    const int kseg = (tid & 3) * 8;
    const int ks = kseg >> 4;
    const int hi = (kseg >> 3) & 1;
    const int r0 = m0 + sm16 * 16 + sg;
    const int r1 = r0 + 8;
    uint32_t* dst = g_At + (size_t)tile * NCHUNK * CH_U32;

    #pragma unroll 1
    for (int c = 0; c < NCHUNK; ++c) {
        const int k0 = c * BK + kseg;
        float v0[8] = {0,0,0,0,0,0,0,0}, v1[8] = {0,0,0,0,0,0,0,0};
        if (r0 < N_ROWS) {
            *(float4*)(v0)     = *(const float4*)(A + (size_t)r0 * IN_CH + k0);
            *(float4*)(v0 + 4) = *(const float4*)(A + (size_t)r0 * IN_CH + k0 + 4);
        }
        if (r1 < N_ROWS) {
            *(float4*)(v1)     = *(const float4*)(A + (size_t)r1 * IN_CH + k0);
            *(float4*)(v1 + 4) = *(const float4*)(A + (size_t)r1 * IN_CH + k0 + 4);
        }
        #pragma unroll
        for (int l4 = 0; l4 < 4; ++l4) {
            uint2 p;
            p.x = pack_h2(v0[l4 * 2], v0[l4 * 2 + 1]);   // row r0 -> reg hi*2
            p.y = pack_h2(v1[l4 * 2], v1[l4 * 2 + 1]);   // row r1 -> reg hi*2+1
            *(uint2*)(dst + c * CH_U32 + aIdx(ks, sm16, sg, l4, hi * 2)) = p;
        }
    }
}

// ---------------------------------------------------------------------------
// pack W: [8][256][128] fp32 -> fp16 B fragments per [kb][chunk]
__global__ __launch_bounds__(256)
void prep_Wt(const float* __restrict__ W)
{
    int d = blockIdx.x * blockDim.x + threadIdx.x;   // 0 .. 8*8*2048-1
    int kb = d >> 14;
    int c  = (d >> 11) & 7;
    int r  = d & 2047;
    int j   = r & 1;
    int l4  = (r >> 1) & 3;
    int col = (r >> 3) & 127;
    int ks  = r >> 10;
    int k0 = c * BK + ks * 16 + j * 8 + l4 * 2;
    float w0 = W[((size_t)kb * IN_CH + k0) * OUT_CH + col];
    float w1 = W[((size_t)kb * IN_CH + k0 + 1) * OUT_CH + col];
    g_Wt[d] = pack_h2(w0, w1);
}

// ---------------------------------------------------------------------------
__global__ __launch_bounds__(256, 2)
void gemm_fp16(float* __restrict__ out)
{
    extern __shared__ uint32_t smem[];   // [A0|A1|B0|B1] x 2048 half2

    const int tid  = threadIdx.x;
    const int kb   = blockIdx.x;
    const int tile = blockIdx.y;
    const int m0   = tile * BM;
    const int lane = tid & 31;
    const int wid  = tid >> 5;
    const int wm   = (wid >> 1) * 32;
    const int wn   = (wid & 1) * 64;
    const int m16b = wm >> 4;
    const int g    = lane >> 2;
    const int l4   = lane & 3;

    const uint32_t sA = smem_u32(smem);
    const uint32_t sB = sA + 2 * CH_U32 * 4;

    auto cpPair = [&](int c, int buf) {
        const uint32_t* srcA = g_At + ((size_t)tile * NCHUNK + c) * CH_U32;
        const uint32_t* srcB = g_Wt + ((size_t)kb * NCHUNK + c) * CH_U32;
        uint32_t dA = sA + (buf * CH_U32 + tid * 4) * 4;
        uint32_t dB = sB + (buf * CH_U32 + tid * 4) * 4;
        asm volatile("cp.async.cg.shared.global [%0], [%1], 16;"
                     :: "r"(dA), "l"(srcA + tid * 4) : "memory");
        asm volatile("cp.async.cg.shared.global [%0], [%1], 16;"
                     :: "r"(dA + 4096), "l"(srcA + 1024 + tid * 4) : "memory");
        asm volatile("cp.async.cg.shared.global [%0], [%1], 16;"
                     :: "r"(dB), "l"(srcB + tid * 4) : "memory");
        asm volatile("cp.async.cg.shared.global [%0], [%1], 16;"
                     :: "r"(dB + 4096), "l"(srcB + 1024 + tid * 4) : "memory");
        asm volatile("cp.async.commit_group;" ::: "memory");
    };

    float acc[2][8][4];
    #pragma unroll
    for (int mt = 0; mt < 2; ++mt)
        #pragma unroll
        for (int nt = 0; nt < 8; ++nt)
            #pragma unroll
            for (int i = 0; i < 4; ++i) acc[mt][nt][i] = 0.f;

    cpPair(0, 0);
    cpPair(1, 1);

    #pragma unroll 1
    for (int c = 0; c < NCHUNK; ++c) {
        const int buf = c & 1;
        if (c < NCHUNK - 1) asm volatile("cp.async.wait_group 1;" ::: "memory");
        else                asm volatile("cp.async.wait_group 0;" ::: "memory");
        __syncthreads();

        const uint32_t* Ab = smem + buf * CH_U32;
        const uint32_t* Bb = smem + (2 + buf) * CH_U32;
        #pragma unroll
        for (int ks = 0; ks < 2; ++ks) {
            uint4 a0 = *(const uint4*)(Ab + aIdx(ks, m16b,     g, l4, 0));
            uint4 a1 = *(const uint4*)(Ab + aIdx(ks, m16b + 1, g, l4, 0));
            #pragma unroll
            for (int nt = 0; nt < 8; ++nt) {
                uint2 b = *(const uint2*)(Bb + ((ks * 128 + wn + nt * 8 + g) * 4 + l4) * 2);
                asm volatile(
                    "mma.sync.aligned.m16n8k16.row.col.f32.f16.f16.f32 "
                    "{%0,%1,%2,%3}, {%4,%5,%6,%7}, {%8,%9}, {%0,%1,%2,%3};\n"
                    : "+f"(acc[0][nt][0]), "+f"(acc[0][nt][1]),
                      "+f"(acc[0][nt][2]), "+f"(acc[0][nt][3])
                    : "r"(a0.x), "r"(a0.y), "r"(a0.z), "r"(a0.w),
                      "r"(b.x), "r"(b.y));
                asm volatile(
                    "mma.sync.aligned.m16n8k16.row.col.f32.f16.f16.f32 "
                    "{%0,%1,%2,%3}, {%4,%5,%6,%7}, {%8,%9}, {%0,%1,%2,%3};\n"
                    : "+f"(acc[1][nt][0]), "+f"(acc[1][nt][1]),
                      "+f"(acc[1][nt][2]), "+f"(acc[1][nt][3])
                    : "r"(a1.x), "r"(a1.y), "r"(a1.z), "r"(a1.w),
                      "r"(b.x), "r"(b.y));
            }
        }
        __syncthreads();
        if (c + 2 < NCHUNK) cpPair(c + 2, buf);
    }

    // epilogue: out[(n*8 + kb)*128 + col]
    #pragma unroll
    for (int mt = 0; mt < 2; ++mt) {
        const int r0 = m0 + wm + mt * 16 + g;
        const int r1 = r0 + 8;
        #pragma unroll
        for (int nt = 0; nt < 8; ++nt) {
            const int col = wn + nt * 8 + l4 * 2;
            if (r0 < N_ROWS) {
                *(float2*)(out + ((size_t)r0 * KVOL + kb) * OUT_CH + col) =
                    make_float2(acc[mt][nt][0], acc[mt][nt][1]);
            }
            if (r1 < N_ROWS) {
                *(float2*)(out + ((size_t)r1 * KVOL + kb) * OUT_CH + col) =
                    make_float2(acc[mt][nt][2], acc[mt][nt][3]);
            }
        }
    }
}

// ---------------------------------------------------------------------------
__global__ __launch_bounds__(256)
void coords_kernel(const int* __restrict__ coords, float* __restrict__ out)
{
    int i = blockIdx.x * blockDim.x + threadIdx.x;   // over N_ROWS*KVOL
    if (i >= N_ROWS * KVOL) return;
    int n = i >> 3, k = i & 7;
    int cx = __ldg(coords + n * 3 + 0);
    int cy = __ldg(coords + n * 3 + 1);
    int cz = __ldg(coords + n * 3 + 2);
    out[(size_t)i * 3 + 0] = (float)(2 * cx + ((k >> 2) & 1));
    out[(size_t)i * 3 + 1] = (float)(2 * cy + ((k >> 1) & 1));
    out[(size_t)i * 3 + 2] = (float)(2 * cz + (k & 1));
}

// ---------------------------------------------------------------------------
extern "C" void kernel_launch(void* const* d_in, const int* in_sizes, int n_in,
                              void* d_out, int out_size)
{
    const float* feats  = nullptr;
    const int*   coords = nullptr;
    const float* W      = nullptr;
    for (int i = 0; i < n_in; ++i) {
        if      (in_sizes[i] == N_ROWS * IN_CH)        feats  = (const float*)d_in[i];
        else if (in_sizes[i] == N_ROWS * 3)            coords = (const int*)d_in[i];
        else if (in_sizes[i] == KVOL * IN_CH * OUT_CH) W      = (const float*)d_in[i];
    }
    float* out = (float*)d_out;

    cudaFuncSetAttribute(gemm_fp16,
                         cudaFuncAttributeMaxDynamicSharedMemorySize, SM_U32 * 4);

    prep_At<<<MTILES, 256>>>(feats);
    prep_Wt<<<(KVOL * NCHUNK * CH_U32) / 256, 256>>>(W);

    dim3 grid(KVOL, MTILES);   // kb fastest: 8 CTAs share each A tile in L2
    gemm_fp16<<<grid, 256, SM_U32 * 4>>>(out);

    const long long featsN = (long long)N_ROWS * KVOL * OUT_CH;
    const long long coordN = (long long)N_ROWS * KVOL * 3;
    if ((long long)out_size >= featsN + coordN && coords != nullptr) {
        const int total = N_ROWS * KVOL;
        coords_kernel<<<(total + 255) / 256, 256>>>(coords, out + featsN);
    }
}

// round 5
// speedup vs baseline: 2.2309x; 1.0637x over previous
#include <cuda_runtime.h>
#include <cuda_fp16.h>
#include <cstdint>

#define N_ROWS 100000
#define IN_CH  256
#define OUT_CH 128
#define KVOL   8

#define BM 128
#define BK 32
#define NCHUNK 8                 // IN_CH / BK
#define MTILES 782               // ceil(100000/128)

// fragment-packed tiles, half2 units (uint32)
// A chunk tile: [ks(2)][m16(8)][g(8)][l4(4)][reg(4)] = 2048 half2 = 8KB
// B chunk tile: [ks(2)][col(128)][l4(4)][j(2)]        = 2048 half2 = 8KB
#define CH_U32 2048
#define SM_U32 (4 * CH_U32)      // 2 bufs A + 2 bufs B = 32KB

__device__ __align__(16) uint32_t g_At[MTILES * NCHUNK * CH_U32];   // 51.25MB
__device__ __align__(16) uint32_t g_Wt[KVOL * NCHUNK * CH_U32];     // 512KB

__device__ __forceinline__ uint32_t pack_h2(float a, float b) {
    __half2 h = __floats2half2_rn(a, b);
    return *reinterpret_cast<uint32_t*>(&h);
}
__device__ __forceinline__ uint32_t smem_u32(const void* p) {
    uint32_t a;
    asm("{ .reg .u64 t; cvta.to.shared.u64 t, %1; cvt.u32.u64 %0, t; }" : "=r"(a) : "l"(p));
    return a;
}
__device__ __forceinline__ int aIdx(int ks, int m16, int g, int l4, int reg) {
    return (((ks * 8 + m16) * 8 + g) * 4 + l4) * 4 + reg;
}

// ---------------------------------------------------------------------------
// pack A: [100000,256] fp32 -> per-tile fp16 MMA fragments
__global__ __launch_bounds__(256)
void prep_At(const float* __restrict__ A)
{
    const int tile = blockIdx.x;
    const int m0 = tile * BM;
    const int tid = threadIdx.x;
    const int pr = tid >> 2;
    const int sm16 = pr >> 3;
    const int sg = pr & 7;
    const int kseg = (tid & 3) * 8;
    const int ks = kseg >> 4;
    const int hi = (kseg >> 3) & 1;
    const int r0 = m0 + sm16 * 16 + sg;
    const int r1 = r0 + 8;
    uint32_t* dst = g_At + (size_t)tile * NCHUNK * CH_U32;

    #pragma unroll 1
    for (int c = 0; c < NCHUNK; ++c) {
        const int k0 = c * BK + kseg;
        float v0[8] = {0,0,0,0,0,0,0,0}, v1[8] = {0,0,0,0,0,0,0,0};
        if (r0 < N_ROWS) {
            *(float4*)(v0)     = *(const float4*)(A + (size_t)r0 * IN_CH + k0);
            *(float4*)(v0 + 4) = *(const float4*)(A + (size_t)r0 * IN_CH + k0 + 4);
        }
        if (r1 < N_ROWS) {
            *(float4*)(v1)     = *(const float4*)(A + (size_t)r1 * IN_CH + k0);
            *(float4*)(v1 + 4) = *(const float4*)(A + (size_t)r1 * IN_CH + k0 + 4);
        }
        #pragma unroll
        for (int l4 = 0; l4 < 4; ++l4) {
            uint2 p;
            p.x = pack_h2(v0[l4 * 2], v0[l4 * 2 + 1]);   // row r0 -> reg hi*2
            p.y = pack_h2(v1[l4 * 2], v1[l4 * 2 + 1]);   // row r1 -> reg hi*2+1
            *(uint2*)(dst + c * CH_U32 + aIdx(ks, sm16, sg, l4, hi * 2)) = p;
        }
    }
}

// ---------------------------------------------------------------------------
// pack W: [8][256][128] fp32 -> fp16 B fragments per [kb][chunk]
__global__ __launch_bounds__(256)
void prep_Wt(const float* __restrict__ W)
{
    int d = blockIdx.x * blockDim.x + threadIdx.x;   // 0 .. 8*8*2048-1
    int kb = d >> 14;
    int c  = (d >> 11) & 7;
    int r  = d & 2047;
    int j   = r & 1;
    int l4  = (r >> 1) & 3;
    int col = (r >> 3) & 127;
    int ks  = r >> 10;
    int k0 = c * BK + ks * 16 + j * 8 + l4 * 2;
    float w0 = W[((size_t)kb * IN_CH + k0) * OUT_CH + col];
    float w1 = W[((size_t)kb * IN_CH + k0 + 1) * OUT_CH + col];
    g_Wt[d] = pack_h2(w0, w1);
}

// ---------------------------------------------------------------------------
// 4 warps, each computing a 64x64 output tile (acc = 128 regs/lane)
__global__ __launch_bounds__(128, 2)
void gemm_fp16(float* __restrict__ out)
{
    extern __shared__ uint32_t smem[];   // [A0|A1|B0|B1] x 2048 half2

    const int tid  = threadIdx.x;
    const int kb   = blockIdx.x;
    const int tile = blockIdx.y;
    const int m0   = tile * BM;
    const int lane = tid & 31;
    const int wid  = tid >> 5;
    const int wm   = (wid >> 1) * 64;       // warp M offset
    const int wn   = (wid & 1) * 64;        // warp N offset
    const int m16b = wm >> 4;               // 0 or 4
    const int g    = lane >> 2;
    const int l4   = lane & 3;

    const uint32_t sA = smem_u32(smem);
    const uint32_t sB = sA + 2 * CH_U32 * 4;

    auto cpPair = [&](int c, int buf) {
        const uint32_t* srcA = g_At + ((size_t)tile * NCHUNK + c) * CH_U32;
        const uint32_t* srcB = g_Wt + ((size_t)kb * NCHUNK + c) * CH_U32;
        uint32_t dA = sA + (buf * CH_U32 + tid * 4) * 4;
        uint32_t dB = sB + (buf * CH_U32 + tid * 4) * 4;
        #pragma unroll
        for (int i = 0; i < 4; ++i) {
            asm volatile("cp.async.cg.shared.global [%0], [%1], 16;"
                         :: "r"(dA + i * 2048), "l"(srcA + tid * 4 + i * 512) : "memory");
            asm volatile("cp.async.cg.shared.global [%0], [%1], 16;"
                         :: "r"(dB + i * 2048), "l"(srcB + tid * 4 + i * 512) : "memory");
        }
        asm volatile("cp.async.commit_group;" ::: "memory");
    };

    float acc[4][8][4];
    #pragma unroll
    for (int mt = 0; mt < 4; ++mt)
        #pragma unroll
        for (int nt = 0; nt < 8; ++nt)
            #pragma unroll
            for (int i = 0; i < 4; ++i) acc[mt][nt][i] = 0.f;

    cpPair(0, 0);
    cpPair(1, 1);

    #pragma unroll 1
    for (int c = 0; c < NCHUNK; ++c) {
        const int buf = c & 1;
        if (c < NCHUNK - 1) asm volatile("cp.async.wait_group 1;" ::: "memory");
        else                asm volatile("cp.async.wait_group 0;" ::: "memory");
        __syncthreads();

        const uint32_t* Ab = smem + buf * CH_U32;
        const uint32_t* Bb = smem + (2 + buf) * CH_U32;
        #pragma unroll
        for (int ks = 0; ks < 2; ++ks) {
            uint4 a[4];
            #pragma unroll
            for (int mt = 0; mt < 4; ++mt)
                a[mt] = *(const uint4*)(Ab + aIdx(ks, m16b + mt, g, l4, 0));
            #pragma unroll
            for (int nt = 0; nt < 8; ++nt) {
                uint2 b = *(const uint2*)(Bb + ((ks * 128 + wn + nt * 8 + g) * 4 + l4) * 2);
                #pragma unroll
                for (int mt = 0; mt < 4; ++mt) {
                    asm volatile(
                        "mma.sync.aligned.m16n8k16.row.col.f32.f16.f16.f32 "
                        "{%0,%1,%2,%3}, {%4,%5,%6,%7}, {%8,%9}, {%0,%1,%2,%3};\n"
                        : "+f"(acc[mt][nt][0]), "+f"(acc[mt][nt][1]),
                          "+f"(acc[mt][nt][2]), "+f"(acc[mt][nt][3])
                        : "r"(a[mt].x), "r"(a[mt].y), "r"(a[mt].z), "r"(a[mt].w),
                          "r"(b.x), "r"(b.y));
                }
            }
        }
        __syncthreads();
        if (c + 2 < NCHUNK) cpPair(c + 2, buf);
    }

    // epilogue: out[(n*8 + kb)*128 + col]
    #pragma unroll
    for (int mt = 0; mt < 4; ++mt) {
        const int r0 = m0 + wm + mt * 16 + g;
        const int r1 = r0 + 8;
        #pragma unroll
        for (int nt = 0; nt < 8; ++nt) {
            const int col = wn + nt * 8 + l4 * 2;
            if (r0 < N_ROWS) {
                *(float2*)(out + ((size_t)r0 * KVOL + kb) * OUT_CH + col) =
                    make_float2(acc[mt][nt][0], acc[mt][nt][1]);
            }
            if (r1 < N_ROWS) {
                *(float2*)(out + ((size_t)r1 * KVOL + kb) * OUT_CH + col) =
                    make_float2(acc[mt][nt][2], acc[mt][nt][3]);
            }
        }
    }
}

// ---------------------------------------------------------------------------
// one thread per input row: 24 contiguous floats -> 6 float4 stores
__global__ __launch_bounds__(256)
void coords_kernel(const int* __restrict__ coords, float* __restrict__ out)
{
    int n = blockIdx.x * blockDim.x + threadIdx.x;
    if (n >= N_ROWS) return;
    float cx = (float)(2 * __ldg(coords + n * 3 + 0));
    float cy = (float)(2 * __ldg(coords + n * 3 + 1));
    float cz = (float)(2 * __ldg(coords + n * 3 + 2));
    float v[24];
    #pragma unroll
    for (int k = 0; k < 8; ++k) {
        v[k * 3 + 0] = cx + (float)((k >> 2) & 1);
        v[k * 3 + 1] = cy + (float)((k >> 1) & 1);
        v[k * 3 + 2] = cz + (float)(k & 1);
    }
    float4* dst = (float4*)(out + (size_t)n * 24);
    #pragma unroll
    for (int i = 0; i < 6; ++i) dst[i] = *(const float4*)(v + i * 4);
}

// ---------------------------------------------------------------------------
extern "C" void kernel_launch(void* const* d_in, const int* in_sizes, int n_in,
                              void* d_out, int out_size)
{
    const float* feats  = nullptr;
    const int*   coords = nullptr;
    const float* W      = nullptr;
    for (int i = 0; i < n_in; ++i) {
        if      (in_sizes[i] == N_ROWS * IN_CH)        feats  = (const float*)d_in[i];
        else if (in_sizes[i] == N_ROWS * 3)            coords = (const int*)d_in[i];
        else if (in_sizes[i] == KVOL * IN_CH * OUT_CH) W      = (const float*)d_in[i];
    }
    float* out = (float*)d_out;

    cudaFuncSetAttribute(gemm_fp16,
                         cudaFuncAttributeMaxDynamicSharedMemorySize, SM_U32 * 4);

    prep_At<<<MTILES, 256>>>(feats);
    prep_Wt<<<(KVOL * NCHUNK * CH_U32) / 256, 256>>>(W);

    dim3 grid(KVOL, MTILES);   // kb fastest: 8 CTAs share each A tile in L2
    gemm_fp16<<<grid, 128, SM_U32 * 4>>>(out);

    const long long featsN = (long long)N_ROWS * KVOL * OUT_CH;
    const long long coordN = (long long)N_ROWS * KVOL * 3;
    if ((long long)out_size >= featsN + coordN && coords != nullptr) {
        coords_kernel<<<(N_ROWS + 255) / 256, 256>>>(coords, out + featsN);
    }
}